// round 13
// baseline (speedup 1.0000x reference)
#include <cuda_runtime.h>
#include <cstdint>

#define B_   8
#define NQ_  75
#define NS_  5
#define NG_  4
#define NF_  49
#define C_   64

#define ROWS_ 294
#define STR_  68
#define NT2_  320

#define NEG_L2E8  (-0.18033688011112042f)   // -0.125*log2(e)
#define POS_L2E4  ( 0.36067376022224084f)   //  0.25*log2(e)

__device__ float g_p1[B_ * NQ_ * NS_ * NG_];
__device__ float g_p2[B_ * NQ_ * NS_ * NG_];
__device__ float g_kss[B_ * NS_ * NG_ * NF_ * NF_];

// upper-triangle 7x7-tile enumeration for the symmetric Kqq block
__constant__ unsigned char QTI_[28] = {0,0,0,0,0,0,0, 1,1,1,1,1,1, 2,2,2,2,2, 3,3,3,3, 4,4,4, 5,5, 6};
__constant__ unsigned char QTJ_[28] = {0,1,2,3,4,5,6, 1,2,3,4,5,6, 2,3,4,5,6, 3,4,5,6, 4,5,6, 5,6, 6};

__device__ __forceinline__ float mg_from_arg(float arg) {
    float t;
    asm("ex2.approx.f32 %0, %1;" : "=f"(t) : "f"(arg));
    float t2 = t * t;
    float s1 = fmaf(t, t, t);
    float t4 = t2 * t2;
    float t8 = t4 * t4;
    float s2 = fmaf(t8, t8, t8);
    return (s1 + t4) + s2;
}

// ---------------------------------------------------------------------------
// k1a: per (b,s,g) -> Kss (49x49) once -> g_kss. 13x13 grid of 4x4 tiles.
// ---------------------------------------------------------------------------
__global__ __launch_bounds__(192) void k1a_kss(const float* __restrict__ sup) {
    __shared__ float xs[52 * STR_];
    __shared__ float ssq[52];

    int bid = blockIdx.x;
    int tid = threadIdx.x;

    const float* sb = sup + (size_t)bid * 49 * 64;
    for (int idx = tid; idx < 52 * 16; idx += 192) {
        int r = idx >> 4, c4 = idx & 15;
        float4 v = make_float4(0.f, 0.f, 0.f, 0.f);
        if (r < 49) v = *(const float4*)(sb + r * 64 + c4 * 4);
        *(float4*)(xs + r * STR_ + c4 * 4) = v;
    }
    __syncthreads();

    if (tid < 52) {
        const float2* xr = (const float2*)(xs + tid * STR_);
        float a0 = 0.f, a1 = 0.f;
        #pragma unroll
        for (int c = 0; c < 32; c++) { float2 x = xr[c]; a0 = fmaf(x.x, x.x, a0); a1 = fmaf(x.y, x.y, a1); }
        ssq[tid] = NEG_L2E8 * (a0 + a1);
    }
    __syncthreads();

    if (tid < 169) {
        int it = tid / 13, jt = tid - it * 13;
        float acc[16];
        #pragma unroll
        for (int k = 0; k < 16; k++) acc[k] = 0.f;
        const float2* A  = (const float2*)(xs + it * 4 * STR_);
        const float2* Bm = (const float2*)(xs + jt * 4 * STR_);
        #pragma unroll 2
        for (int c2 = 0; c2 < 32; c2++) {
            float2 a[4], bb[4];
            #pragma unroll
            for (int k = 0; k < 4; k++) a[k]  = A[k * (STR_ / 2) + c2];
            #pragma unroll
            for (int k = 0; k < 4; k++) bb[k] = Bm[k * (STR_ / 2) + c2];
            #pragma unroll
            for (int ii = 0; ii < 4; ii++)
                #pragma unroll
                for (int jj = 0; jj < 4; jj++) {
                    acc[ii * 4 + jj] = fmaf(a[ii].x, bb[jj].x, acc[ii * 4 + jj]);
                    acc[ii * 4 + jj] = fmaf(a[ii].y, bb[jj].y, acc[ii * 4 + jj]);
                }
        }
        float* kout = g_kss + (size_t)bid * 2401;
        #pragma unroll
        for (int ii = 0; ii < 4; ii++) {
            int i = it * 4 + ii;
            if (i < 49) {
                float ai = ssq[i];
                #pragma unroll
                for (int jj = 0; jj < 4; jj++) {
                    int j = jt * 4 + jj;
                    if (j < 49) {
                        float arg = fmaf(POS_L2E4, acc[ii * 4 + jj], ai + ssq[j]);
                        kout[i * 49 + j] = mg_from_arg(arg);
                    }
                }
            }
        }
    }
}

// ---------------------------------------------------------------------------
// k1b: per (b,s,g,vchunk of 15) -> beta^T Kss beta (Kss L2-hot)
// ---------------------------------------------------------------------------
__global__ __launch_bounds__(256) void k1b_bilinear(const float* __restrict__ beta) {
    __shared__ float kss[49 * 50];
    __shared__ float betas[15 * 50];
    __shared__ float scr[735];

    int bid = blockIdx.x;
    int g = bid & 3;
    int rest = bid >> 2;
    int s = rest % NS_;  rest /= NS_;
    int vt = rest % 5;
    int b = rest / 5;
    int tid = threadIdx.x;

    int bid160 = (b * NS_ + s) * NG_ + g;
    const float* ksrc = g_kss + (size_t)bid160 * 2401;
    for (int idx = tid; idx < 2401; idx += 256) {
        int i = idx / 49, j = idx - i * 49;
        kss[i * 50 + j] = ksrc[idx];
    }
    for (int idx = tid; idx < 15 * 49; idx += 256) {
        int vv = idx / 49, j = idx - vv * 49;
        int v = vt * 15 + vv;
        size_t off = ((size_t)((b * NQ_ + v) * NS_ + s) * NG_ + g) * 49 + j;
        betas[vv * 50 + j] = beta[off];
    }
    __syncthreads();

    for (int t = tid; t < 735; t += 256) {
        int vv = t / 49, i = t - vv * 49;
        const float2* kr = (const float2*)(kss + i * 50);
        const float2* bv = (const float2*)(betas + vv * 50);
        float r0 = 0.f, r1 = 0.f;
        #pragma unroll
        for (int c = 0; c < 24; c++) {
            float2 kk = kr[c], bb = bv[c];
            r0 = fmaf(kk.x, bb.x, r0);
            r1 = fmaf(kk.y, bb.y, r1);
        }
        float r = r0 + r1 + kss[i * 50 + 48] * betas[vv * 50 + 48];
        scr[t] = betas[vv * 50 + i] * r;
    }
    __syncthreads();

    if (tid < 15) {
        float acc = 0.f;
        #pragma unroll
        for (int k = 0; k < 49; k++) acc += scr[tid * 49 + k];
        int v = vt * 15 + tid;
        g_p1[((b * NQ_ + v) * NS_ + s) * NG_ + g] = acc;
    }
}

// ---------------------------------------------------------------------------
// k2: per (b,v,g). Support tiles: tid 0..244 (35x7 grid). Query (Kqq) tiles:
// upper triangle only, 28 tiles on tid 245..272 (warp 9 idles through the
// heavy loop). Off-diagonal tile bilinears doubled via exact dot symmetry.
// ---------------------------------------------------------------------------
__global__ __launch_bounds__(NT2_, 2) void k2_main(const float* __restrict__ sup,
                                                   const float* __restrict__ qry,
                                                   const float* __restrict__ beta,
                                                   const float* __restrict__ gamma) {
    extern __shared__ float sm[];
    float* xs   = sm;                     // 294*68
    float* rsq  = xs + ROWS_ * STR_;      // 296 (pre-scaled by NEG_L2E8)
    float* bet  = rsq + 296;              // 245
    float* gam  = bet + 245;              // 245
    float* scr  = gam + 245;              // 245
    float* scrq = scr + 245;              // 140 (5 s x 28 tiles)
    float* red  = scrq + 140;             // 16

    int bid = blockIdx.x;
    int g = bid & 3;
    int bv = bid >> 2;
    int b = bv / NQ_;
    int tid = threadIdx.x;

    const float* supb = sup + (size_t)(b * (NS_ * NG_) + g) * 49 * 64;
    const float* qryb = qry + ((size_t)bv * NG_ + g) * 49 * 64;

    for (int idx = tid; idx < ROWS_ * 16; idx += NT2_) {
        int r = idx >> 4, c4 = idx & 15;
        float4 val;
        if (r < 245) {
            int s = r / 49;
            int i = r - s * 49;
            val = *(const float4*)(supb + (size_t)s * (NG_ * 49 * 64) + i * 64 + c4 * 4);
        } else {
            val = *(const float4*)(qryb + (r - 245) * 64 + c4 * 4);
        }
        *(float4*)(xs + r * STR_ + c4 * 4) = val;
    }
    for (int idx = tid; idx < NS_ * 49; idx += NT2_) {
        int s = idx / 49, j = idx - s * 49;
        size_t off = ((size_t)(bv * NS_ + s) * NG_ + g) * 49 + j;
        bet[idx] = beta[off];
        gam[idx] = gamma[off];
    }
    __syncthreads();

    for (int r = tid; r < ROWS_; r += NT2_) {
        const float2* xr = (const float2*)(xs + r * STR_);
        float a0 = 0.f, a1 = 0.f;
        #pragma unroll
        for (int c = 0; c < 32; c++) { float2 x = xr[c]; a0 = fmaf(x.x, x.x, a0); a1 = fmaf(x.y, x.y, a1); }
        rsq[r] = NEG_L2E8 * (a0 + a1);
    }
    __syncthreads();

    bool active = (tid < 273);
    // row/col tile for this thread
    int ib, jb;           // row base (into xs), col tile index jt (0..6)
    int jt;
    bool isq = (tid >= 245);
    if (!isq) {
        int it = tid / 7;
        jt = tid - it * 7;
        ib = it * 7;
    } else {
        int qi = tid - 245;          // 0..27 (or invalid if >=28)
        int ti = (qi < 28) ? QTI_[qi] : 0;
        jt = (qi < 28) ? QTJ_[qi] : 0;
        ib = 245 + ti * 7;
        if (qi >= 28) active = false;
    }

    if (active) {
        float acc[49];
        #pragma unroll
        for (int k = 0; k < 49; k++) acc[k] = 0.0f;

        const float2* A  = (const float2*)(xs + ib * STR_);
        const float2* Bm = (const float2*)(xs + (245 + jt * 7) * STR_);
        #pragma unroll 1
        for (int c2 = 0; c2 < 32; c2++) {
            float2 a[7], bb[7];
            #pragma unroll
            for (int k = 0; k < 7; k++) a[k]  = A[k * (STR_ / 2) + c2];
            #pragma unroll
            for (int k = 0; k < 7; k++) bb[k] = Bm[k * (STR_ / 2) + c2];
            #pragma unroll
            for (int ii = 0; ii < 7; ii++)
                #pragma unroll
                for (int jj = 0; jj < 7; jj++) {
                    acc[ii * 7 + jj] = fmaf(a[ii].x, bb[jj].x, acc[ii * 7 + jj]);
                    acc[ii * 7 + jj] = fmaf(a[ii].y, bb[jj].y, acc[ii * 7 + jj]);
                }
        }

        float qsq[7];
        int jbase = jt * 7;
        #pragma unroll
        for (int jj = 0; jj < 7; jj++) qsq[jj] = rsq[245 + jbase + jj];
        #pragma unroll
        for (int ii = 0; ii < 7; ii++) {
            float ai = rsq[ib + ii];
            #pragma unroll
            for (int jj = 0; jj < 7; jj++) {
                float arg = fmaf(POS_L2E4, acc[ii * 7 + jj], ai + qsq[jj]);
                acc[ii * 7 + jj] = mg_from_arg(arg);
            }
        }

        if (!isq) {
            int s = tid / 49;        // == (tid/7)/7
            int i0 = ib - s * 49;
            const float* gs = gam + s * 49 + jbase;
            const float* bs = bet + s * 49 + i0;
            float partial = 0.0f;
            #pragma unroll
            for (int ii = 0; ii < 7; ii++) {
                float rowsum = 0.0f;
                #pragma unroll
                for (int jj = 0; jj < 7; jj++) rowsum = fmaf(acc[ii * 7 + jj], gs[jj], rowsum);
                partial = fmaf(bs[ii], rowsum, partial);
            }
            scr[tid] = partial;
        } else {
            int qi = tid - 245;      // 0..27
            int i0 = ib - 245;       // ti*7
            float w = (i0 == jbase) ? 1.0f : 2.0f;
            #pragma unroll
            for (int s = 0; s < 5; s++) {
                const float* gs = gam + s * 49;
                float pq = 0.0f;
                #pragma unroll
                for (int ii = 0; ii < 7; ii++) {
                    float rowsum = 0.0f;
                    #pragma unroll
                    for (int jj = 0; jj < 7; jj++) rowsum = fmaf(acc[ii * 7 + jj], gs[jbase + jj], rowsum);
                    pq = fmaf(gs[i0 + ii], rowsum, pq);
                }
                scrq[s * 28 + qi] = w * pq;
            }
        }
    }
    __syncthreads();

    if (tid < 10) {
        int s = tid % 5;
        float acc2 = 0.f;
        if (tid < 5) {
            const float* src = scr + s * 49;
            #pragma unroll
            for (int k = 0; k < 49; k++) acc2 += src[k];
        } else {
            const float* src = scrq + s * 28;
            #pragma unroll
            for (int k = 0; k < 28; k++) acc2 += src[k];
        }
        red[tid] = acc2;
    }
    __syncthreads();

    if (tid < NS_) {
        int idx = (bv * NS_ + tid) * NG_ + g;
        g_p2[idx] = red[5 + tid] - 2.0f * red[tid];
    }
}

__global__ void k3_reduce(float* __restrict__ out) {
    int o = blockIdx.x * blockDim.x + threadIdx.x;
    if (o < B_ * NQ_ * NS_) {
        float s = 0.0f;
        #pragma unroll
        for (int g = 0; g < NG_; g++) s += g_p1[o * NG_ + g] + g_p2[o * NG_ + g];
        out[o] = 0.25f * s;
    }
}

extern "C" void kernel_launch(void* const* d_in, const int* in_sizes, int n_in,
                              void* d_out, int out_size) {
    const float* sup   = (const float*)d_in[0];
    const float* qry   = (const float*)d_in[1];
    const float* beta  = (const float*)d_in[2];
    const float* gamma = (const float*)d_in[3];
    float* out = (float*)d_out;

    const int smem2 = (ROWS_ * STR_ + 296 + 245 * 3 + 140 + 16) * (int)sizeof(float);
    static bool configured = false;
    if (!configured) {
        cudaFuncSetAttribute(k2_main, cudaFuncAttributeMaxDynamicSharedMemorySize, smem2);
        configured = true;
    }

    k1a_kss<<<B_ * NS_ * NG_, 192>>>(sup);
    k1b_bilinear<<<B_ * NS_ * NG_ * 5, 256>>>(beta);
    k2_main<<<B_ * NQ_ * NG_, NT2_, smem2>>>(sup, qry, beta, gamma);
    k3_reduce<<<(B_ * NQ_ * NS_ + 255) / 256, 256>>>(out);
}